// round 5
// baseline (speedup 1.0000x reference)
#include <cuda_runtime.h>
#include <cuda_fp16.h>
#include <stdint.h>

#define B_SZ   16384
#define N_NODE 12
#define C_DIM  512
#define M_ROWS (B_SZ * N_NODE)   // 196608

// ---------------- scratch (device globals; allocation is forbidden) ----------------
__device__ __half g_z[(size_t)M_ROWS * C_DIM];     // z = alpha @ x  (fp16, 201 MB)
__device__ __half g_wh[C_DIM * C_DIM];             // W in fp16, [k][n] (same layout as W)
__device__ float  g_wa_l[C_DIM];                   // W @ a_l
__device__ float  g_wa_r[C_DIM];                   // W @ a_r

// ADJ_BASE rows as bitmasks (bit j set <=> ADJ_BASE[i][j] == 1)
__constant__ unsigned c_adj_row[12] = {
    0xFE8u, 0xFE8u, 0xFE8u, 0xFF7u, 0xFE8u, 0x1DFu,
    0xE3Fu, 0xE3Fu, 0xE3Fu, 0x1DFu, 0x1DFu, 0x1DFu
};

__device__ __forceinline__ uint32_t smem_u32(const void* p) {
    return (uint32_t)__cvta_generic_to_shared(p);
}

// ---------------- kernel 0a: W -> fp16 ----------------
__global__ void prep_w_kernel(const float* __restrict__ W) {
    int i = blockIdx.x * 512 + threadIdx.x;
    g_wh[i] = __float2half(W[i]);
}

// ---------------- kernel 0b: wa_l = W @ a_l, wa_r = W @ a_r (warp per k) ----------------
__global__ void prep_wa_kernel(const float* __restrict__ W,
                               const float* __restrict__ a_l,
                               const float* __restrict__ a_r) {
    int k = blockIdx.x * 8 + (threadIdx.x >> 5);   // 64 blocks * 8 warps = 512
    int lid = threadIdx.x & 31;
    const float* wr = W + (size_t)k * 512;
    float sl = 0.f, sr = 0.f;
    #pragma unroll
    for (int j = 0; j < 16; j++) {
        int n = lid + j * 32;
        float wv = wr[n];
        sl += wv * __ldg(a_l + n);
        sr += wv * __ldg(a_r + n);
    }
    #pragma unroll
    for (int o = 16; o; o >>= 1) {
        sl += __shfl_xor_sync(0xFFFFFFFFu, sl, o);
        sr += __shfl_xor_sync(0xFFFFFFFFu, sr, o);
    }
    if (lid == 0) { g_wa_l[k] = sl; g_wa_r[k] = sr; }
}

// ---------------- kernel 1: per-batch attention -> z = alpha @ x (fp16) ----------------
__global__ void __launch_bounds__(128) attn_kernel(const float* __restrict__ x,
                                                   const float* __restrict__ adj_mask) {
    __shared__ float x_s[12 * 512];
    __shared__ float s_el[12], s_er[12];
    __shared__ float alpha_s[12][12];
    const int b = blockIdx.x;
    const int tid = threadIdx.x;
    const int wid = tid >> 5;
    const int lid = tid & 31;

    // load x for this batch (24 KB)
    const float4* xsrc = (const float4*)(x + (size_t)b * 6144);
    float4* xdst = (float4*)x_s;
    #pragma unroll
    for (int it = 0; it < 12; it++) xdst[tid + it * 128] = xsrc[tid + it * 128];
    __syncthreads();

    // el_i = x_i . wa_l, er_i = x_i . wa_r   (warp w handles rows w, w+4, w+8)
    #pragma unroll
    for (int rr = 0; rr < 3; rr++) {
        int row = wid + rr * 4;
        const float* xr = x_s + row * 512;
        float sl = 0.f, sr = 0.f;
        #pragma unroll
        for (int j = 0; j < 16; j++) {
            int d = lid + j * 32;
            float xv = xr[d];
            sl += xv * g_wa_l[d];
            sr += xv * g_wa_r[d];
        }
        #pragma unroll
        for (int o = 16; o; o >>= 1) {
            sl += __shfl_xor_sync(0xFFFFFFFFu, sl, o);
            sr += __shfl_xor_sync(0xFFFFFFFFu, sr, o);
        }
        if (lid == 0) { s_el[row] = sl; s_er[row] = sr; }
    }
    __syncthreads();

    // masked softmax (one thread per output node)
    if (tid < 12) {
        const int i = tid;
        const unsigned rm = c_adj_row[i];
        const float eli = s_el[i];
        const float* am = adj_mask + (size_t)b * 144 + i * 12;
        float ev[12];
        bool keep[12];
        float mx = -3.4e38f;
        #pragma unroll
        for (int j = 0; j < 12; j++) {
            keep[j] = (j == i) || ((((rm >> j) & 1u) != 0u) && (am[j] > 0.1f));
            float v = eli + s_er[j];
            v = (v > 0.f) ? v : 0.2f * v;      // leaky_relu(0.2)
            ev[j] = v;
            if (keep[j] && v > mx) mx = v;
        }
        float s = 0.f;
        #pragma unroll
        for (int j = 0; j < 12; j++) {
            float v = keep[j] ? expf(ev[j] - mx) : 0.f;
            alpha_s[i][j] = v;
            s += v;
        }
        float inv = 1.f / s;
        #pragma unroll
        for (int j = 0; j < 12; j++) alpha_s[i][j] *= inv;
    }
    __syncthreads();

    // z = alpha @ x, write fp16. Thread t owns cols 4t..4t+3.
    float4 acc[12];
    #pragma unroll
    for (int n = 0; n < 12; n++) acc[n] = make_float4(0.f, 0.f, 0.f, 0.f);
    const float4* xs4 = (const float4*)x_s;
    #pragma unroll
    for (int m = 0; m < 12; m++) {
        float4 xv = xs4[m * 128 + tid];
        #pragma unroll
        for (int n = 0; n < 12; n++) {
            float a = alpha_s[n][m];
            acc[n].x += a * xv.x;
            acc[n].y += a * xv.y;
            acc[n].z += a * xv.z;
            acc[n].w += a * xv.w;
        }
    }
    #pragma unroll
    for (int n = 0; n < 12; n++) {
        __half2 p0 = __floats2half2_rn(acc[n].x, acc[n].y);
        __half2 p1 = __floats2half2_rn(acc[n].z, acc[n].w);
        uint2 u;
        u.x = *reinterpret_cast<uint32_t*>(&p0);
        u.y = *reinterpret_cast<uint32_t*>(&p1);
        *reinterpret_cast<uint2*>(g_z + (size_t)(b * 12 + n) * 512 + tid * 4) = u;
    }
}

// ---------------- kernel 2: out = z @ W + x  (mma.sync fp16, fp32 accum) ----------------
// CTA tile 128(M) x 64(N), k-chunks of 32, double-buffered cp.async.
// 8 warps as 4(M) x 2(N); warp tile 32x32; per warp: 2 m-tiles x 4 n-tiles (m16n8k16).
#define A_STRIDE 40    // halves per A smem row (80 B) -> conflict-free ldmatrix
#define B_STRIDE 72    // halves per B smem row (144 B)
#define A_BUF_H  (128 * A_STRIDE)   // 5120 halves = 10240 B
#define B_BUF_H  (32 * B_STRIDE)    // 2304 halves = 4608 B

__global__ void __launch_bounds__(256, 2) gemm_kernel(const float* __restrict__ x,
                                                      float* __restrict__ out) {
    __shared__ __half As[2][A_BUF_H];
    __shared__ __half Bs[2][B_BUF_H];

    const int tid = threadIdx.x;
    const int wid = tid >> 5;
    const int lid = tid & 31;
    const int warp_m = wid & 3;
    const int warp_n = wid >> 2;
    const int m0 = blockIdx.y * 128;
    const int n0 = blockIdx.x * 64;

    const uint32_t sA = smem_u32(As);
    const uint32_t sB = smem_u32(Bs);

    // cp.async dst offsets (bytes)
    const int ac0 = tid, ac1 = tid + 256;           // A: 512 chunks of 16B
    const uint32_t adst0 = sA + (uint32_t)((ac0 >> 2) * 80 + (ac0 & 3) * 16);
    const uint32_t adst1 = sA + (uint32_t)((ac1 >> 2) * 80 + (ac1 & 3) * 16);
    const uint32_t bdst  = sB + (uint32_t)((tid >> 3) * 144 + (tid & 7) * 16);
    const __half* asrc0 = g_z + (size_t)(m0 + (ac0 >> 2)) * 512 + (ac0 & 3) * 8;
    const __half* asrc1 = g_z + (size_t)(m0 + (ac1 >> 2)) * 512 + (ac1 & 3) * 8;
    const __half* bsrc  = g_wh + (size_t)(tid >> 3) * 512 + n0 + (tid & 7) * 8;

    // ldmatrix per-lane bases
    const int lm_row = ((lid >> 3) & 1) * 8 + (lid & 7);
    const int lm_col = (lid >> 4) * 16;             // bytes
    const uint32_t a_lm = sA + (uint32_t)((warp_m * 32 + lm_row) * 80 + lm_col);
    const uint32_t b_lm = sB + (uint32_t)(lm_row * 144 + warp_n * 64 + lm_col);

    float c[2][4][4];
    #pragma unroll
    for (int mt = 0; mt < 2; mt++)
        #pragma unroll
        for (int nt = 0; nt < 4; nt++)
            #pragma unroll
            for (int e = 0; e < 4; e++) c[mt][nt][e] = 0.f;

    // prologue: load chunk 0 into buf 0
    asm volatile("cp.async.cg.shared.global [%0], [%1], 16;" :: "r"(adst0), "l"(asrc0));
    asm volatile("cp.async.cg.shared.global [%0], [%1], 16;" :: "r"(adst1), "l"(asrc1));
    asm volatile("cp.async.cg.shared.global [%0], [%1], 16;" :: "r"(bdst),  "l"(bsrc));
    asm volatile("cp.async.commit_group;");

    #pragma unroll 1
    for (int kc = 0; kc < 16; kc++) {
        if (kc < 15) {
            int buf = (kc + 1) & 1;
            asm volatile("cp.async.cg.shared.global [%0], [%1], 16;"
                         :: "r"(adst0 + buf * 10240u), "l"(asrc0 + (kc + 1) * 32));
            asm volatile("cp.async.cg.shared.global [%0], [%1], 16;"
                         :: "r"(adst1 + buf * 10240u), "l"(asrc1 + (kc + 1) * 32));
            asm volatile("cp.async.cg.shared.global [%0], [%1], 16;"
                         :: "r"(bdst + buf * 4608u), "l"(bsrc + (size_t)(kc + 1) * 32 * 512));
            asm volatile("cp.async.commit_group;");
            asm volatile("cp.async.wait_group 1;");
        } else {
            asm volatile("cp.async.wait_group 0;");
        }
        __syncthreads();

        const uint32_t abuf = a_lm + (kc & 1) * 10240u;
        const uint32_t bbuf = b_lm + (kc & 1) * 4608u;
        #pragma unroll
        for (int ks = 0; ks < 2; ks++) {
            uint32_t a[2][4], bf[4][2];
            #pragma unroll
            for (int mt = 0; mt < 2; mt++) {
                asm volatile("ldmatrix.sync.aligned.m8n8.x4.shared.b16 {%0,%1,%2,%3}, [%4];"
                             : "=r"(a[mt][0]), "=r"(a[mt][1]), "=r"(a[mt][2]), "=r"(a[mt][3])
                             : "r"(abuf + (uint32_t)(mt * 16 * 80 + ks * 32)));
            }
            #pragma unroll
            for (int i = 0; i < 2; i++) {
                asm volatile("ldmatrix.sync.aligned.m8n8.x4.trans.shared.b16 {%0,%1,%2,%3}, [%4];"
                             : "=r"(bf[2*i][0]), "=r"(bf[2*i][1]),
                               "=r"(bf[2*i+1][0]), "=r"(bf[2*i+1][1])
                             : "r"(bbuf + (uint32_t)(ks * 16 * 144 + i * 32)));
            }
            #pragma unroll
            for (int mt = 0; mt < 2; mt++)
                #pragma unroll
                for (int nt = 0; nt < 4; nt++) {
                    asm volatile(
                        "mma.sync.aligned.m16n8k16.row.col.f32.f16.f16.f32 "
                        "{%0,%1,%2,%3}, {%4,%5,%6,%7}, {%8,%9}, {%0,%1,%2,%3};"
                        : "+f"(c[mt][nt][0]), "+f"(c[mt][nt][1]),
                          "+f"(c[mt][nt][2]), "+f"(c[mt][nt][3])
                        : "r"(a[mt][0]), "r"(a[mt][1]), "r"(a[mt][2]), "r"(a[mt][3]),
                          "r"(bf[nt][0]), "r"(bf[nt][1]));
                }
        }
        __syncthreads();
    }

    // epilogue: out = c + x
    const int rbase = m0 + warp_m * 32 + (lid >> 2);
    const int cbase = n0 + warp_n * 32 + (lid & 3) * 2;
    #pragma unroll
    for (int mt = 0; mt < 2; mt++) {
        #pragma unroll
        for (int nt = 0; nt < 4; nt++) {
            int col = cbase + nt * 8;
            {
                size_t o = (size_t)(rbase + mt * 16) * 512 + col;
                float2 xv = *reinterpret_cast<const float2*>(x + o);
                float2 r = make_float2(c[mt][nt][0] + xv.x, c[mt][nt][1] + xv.y);
                *reinterpret_cast<float2*>(out + o) = r;
            }
            {
                size_t o = (size_t)(rbase + mt * 16 + 8) * 512 + col;
                float2 xv = *reinterpret_cast<const float2*>(x + o);
                float2 r = make_float2(c[mt][nt][2] + xv.x, c[mt][nt][3] + xv.y);
                *reinterpret_cast<float2*>(out + o) = r;
            }
        }
    }
}

// ---------------- launch ----------------
extern "C" void kernel_launch(void* const* d_in, const int* in_sizes, int n_in,
                              void* d_out, int out_size) {
    const float* x        = (const float*)d_in[0];
    const float* adj_mask = (const float*)d_in[1];
    const float* W        = (const float*)d_in[2];
    const float* a_l      = (const float*)d_in[3];
    const float* a_r      = (const float*)d_in[4];
    float* out = (float*)d_out;

    prep_w_kernel<<<512, 512>>>(W);
    prep_wa_kernel<<<64, 256>>>(W, a_l, a_r);
    attn_kernel<<<B_SZ, 128>>>(x, adj_mask);
    gemm_kernel<<<dim3(8, 1536), 256>>>(x, out);
}

// round 9
// speedup vs baseline: 1.2036x; 1.2036x over previous
#include <cuda_runtime.h>
#include <cuda_fp16.h>
#include <stdint.h>

#define B_SZ   16384
#define N_NODE 12
#define C_DIM  512
#define M_ROWS (B_SZ * N_NODE)   // 196608

// ---------------- scratch (device globals; allocation is forbidden) ----------------
__device__ __half g_z[(size_t)M_ROWS * C_DIM];     // z = alpha @ x  (fp16, 201 MB)
__device__ __half g_wh[C_DIM * C_DIM];             // W in fp16, [k][n]
__device__ float  g_wa_l[C_DIM];                   // W @ a_l
__device__ float  g_wa_r[C_DIM];                   // W @ a_r

// ADJ_BASE rows as bitmasks (bit j set <=> ADJ_BASE[i][j] == 1)
__constant__ unsigned c_adj_row[12] = {
    0xFE8u, 0xFE8u, 0xFE8u, 0xFF7u, 0xFE8u, 0x1DFu,
    0xE3Fu, 0xE3Fu, 0xE3Fu, 0x1DFu, 0x1DFu, 0x1DFu
};

__device__ __forceinline__ uint32_t smem_u32(const void* p) {
    return (uint32_t)__cvta_generic_to_shared(p);
}

// ---------------- kernel 0a: W -> fp16 ----------------
__global__ void prep_w_kernel(const float* __restrict__ W) {
    int i = blockIdx.x * 512 + threadIdx.x;
    g_wh[i] = __float2half(W[i]);
}

// ---------------- kernel 0b: wa_l = W @ a_l, wa_r = W @ a_r (warp per k) ----------------
__global__ void prep_wa_kernel(const float* __restrict__ W,
                               const float* __restrict__ a_l,
                               const float* __restrict__ a_r) {
    int k = blockIdx.x * 8 + (threadIdx.x >> 5);   // 64 blocks * 8 warps = 512
    int lid = threadIdx.x & 31;
    const float* wr = W + (size_t)k * 512;
    float sl = 0.f, sr = 0.f;
    #pragma unroll
    for (int j = 0; j < 16; j++) {
        int n = lid + j * 32;
        float wv = wr[n];
        sl += wv * __ldg(a_l + n);
        sr += wv * __ldg(a_r + n);
    }
    #pragma unroll
    for (int o = 16; o; o >>= 1) {
        sl += __shfl_xor_sync(0xFFFFFFFFu, sl, o);
        sr += __shfl_xor_sync(0xFFFFFFFFu, sr, o);
    }
    if (lid == 0) { g_wa_l[k] = sl; g_wa_r[k] = sr; }
}

// ---------------- kernel 1: per-batch attention -> z = alpha @ x (fp16) ----------------
__global__ void __launch_bounds__(128) attn_kernel(const float* __restrict__ x,
                                                   const float* __restrict__ adj_mask) {
    __shared__ float x_s[12 * 512];
    __shared__ float s_el[12], s_er[12];
    __shared__ float alpha_s[12][12];
    const int b = blockIdx.x;
    const int tid = threadIdx.x;
    const int wid = tid >> 5;
    const int lid = tid & 31;

    const float4* xsrc = (const float4*)(x + (size_t)b * 6144);
    float4* xdst = (float4*)x_s;
    #pragma unroll
    for (int it = 0; it < 12; it++) xdst[tid + it * 128] = xsrc[tid + it * 128];
    __syncthreads();

    // el_i = x_i . wa_l, er_i = x_i . wa_r   (warp w handles rows w, w+4, w+8)
    #pragma unroll
    for (int rr = 0; rr < 3; rr++) {
        int row = wid + rr * 4;
        const float* xr = x_s + row * 512;
        float sl = 0.f, sr = 0.f;
        #pragma unroll
        for (int j = 0; j < 16; j++) {
            int d = lid + j * 32;
            float xv = xr[d];
            sl += xv * g_wa_l[d];
            sr += xv * g_wa_r[d];
        }
        #pragma unroll
        for (int o = 16; o; o >>= 1) {
            sl += __shfl_xor_sync(0xFFFFFFFFu, sl, o);
            sr += __shfl_xor_sync(0xFFFFFFFFu, sr, o);
        }
        if (lid == 0) { s_el[row] = sl; s_er[row] = sr; }
    }
    __syncthreads();

    if (tid < 12) {
        const int i = tid;
        const unsigned rm = c_adj_row[i];
        const float eli = s_el[i];
        const float* am = adj_mask + (size_t)b * 144 + i * 12;
        float ev[12];
        bool keep[12];
        float mx = -3.4e38f;
        #pragma unroll
        for (int j = 0; j < 12; j++) {
            keep[j] = (j == i) || ((((rm >> j) & 1u) != 0u) && (am[j] > 0.1f));
            float v = eli + s_er[j];
            v = (v > 0.f) ? v : 0.2f * v;      // leaky_relu(0.2)
            ev[j] = v;
            if (keep[j] && v > mx) mx = v;
        }
        float s = 0.f;
        #pragma unroll
        for (int j = 0; j < 12; j++) {
            float v = keep[j] ? expf(ev[j] - mx) : 0.f;
            alpha_s[i][j] = v;
            s += v;
        }
        float inv = 1.f / s;
        #pragma unroll
        for (int j = 0; j < 12; j++) alpha_s[i][j] *= inv;
    }
    __syncthreads();

    // z = alpha @ x, write fp16. Thread t owns cols 4t..4t+3.
    float4 acc[12];
    #pragma unroll
    for (int n = 0; n < 12; n++) acc[n] = make_float4(0.f, 0.f, 0.f, 0.f);
    const float4* xs4 = (const float4*)x_s;
    #pragma unroll
    for (int m = 0; m < 12; m++) {
        float4 xv = xs4[m * 128 + tid];
        #pragma unroll
        for (int n = 0; n < 12; n++) {
            float a = alpha_s[n][m];
            acc[n].x += a * xv.x;
            acc[n].y += a * xv.y;
            acc[n].z += a * xv.z;
            acc[n].w += a * xv.w;
        }
    }
    #pragma unroll
    for (int n = 0; n < 12; n++) {
        __half2 p0 = __floats2half2_rn(acc[n].x, acc[n].y);
        __half2 p1 = __floats2half2_rn(acc[n].z, acc[n].w);
        uint2 u;
        u.x = *reinterpret_cast<uint32_t*>(&p0);
        u.y = *reinterpret_cast<uint32_t*>(&p1);
        *reinterpret_cast<uint2*>(g_z + (size_t)(b * 12 + n) * 512 + tid * 4) = u;
    }
}

// ---------------- kernel 2: out = z @ W + x  (mma.sync fp16, fp32 accum) ----------------
// CTA tile 128(M) x 128(N), k-chunks of 32, 3-stage cp.async pipeline,
// ONE __syncthreads per chunk. 8 warps as 4(M) x 2(N); warp tile 32x64:
// 2 m-tiles x 8 n-tiles of m16n8k16 -> 32 MMA per chunk per warp.
#define A_STRIDE_B  80u      // bytes per A smem row (32 halves + 8 pad)
#define B_STRIDE_B  272u     // bytes per B smem row (128 halves + 8 pad)
#define A_STAGE_B   (128u * A_STRIDE_B)   // 10240
#define B_STAGE_B   (32u  * B_STRIDE_B)   // 8704
#define N_STAGE     3
#define GEMM_SMEM   (N_STAGE * (A_STAGE_B + B_STAGE_B))   // 56832

__global__ void __launch_bounds__(256, 2) gemm_kernel(const float* __restrict__ x,
                                                      float* __restrict__ out) {
    extern __shared__ __align__(16) char smem[];

    const int tid = threadIdx.x;
    const int wid = tid >> 5;
    const int lid = tid & 31;
    const int warp_m = wid & 3;
    const int warp_n = wid >> 2;
    const int m0 = blockIdx.y * 128;
    const int n0 = blockIdx.x * 128;

    const uint32_t sA = smem_u32(smem);
    const uint32_t sB = sA + N_STAGE * A_STAGE_B;

    // ---- cp.async source/dst precompute ----
    // A: 128 rows x 32 cols x 2B = 512 chunks of 16B; 2 per thread.
    const int ac0 = tid, ac1 = tid + 256;
    const uint32_t adst0 = (uint32_t)((ac0 >> 2) * A_STRIDE_B + (ac0 & 3) * 16);
    const uint32_t adst1 = (uint32_t)((ac1 >> 2) * A_STRIDE_B + (ac1 & 3) * 16);
    const __half* asrc0 = g_z + (size_t)(m0 + (ac0 >> 2)) * 512 + (ac0 & 3) * 8;
    const __half* asrc1 = g_z + (size_t)(m0 + (ac1 >> 2)) * 512 + (ac1 & 3) * 8;
    // B: 32 rows x 128 cols x 2B = 512 chunks of 16B; 2 per thread.
    const int bc0 = tid, bc1 = tid + 256;
    const uint32_t bdst0 = (uint32_t)((bc0 >> 4) * B_STRIDE_B + (bc0 & 15) * 16);
    const uint32_t bdst1 = (uint32_t)((bc1 >> 4) * B_STRIDE_B + (bc1 & 15) * 16);
    const __half* bsrc0 = g_wh + (size_t)(bc0 >> 4) * 512 + n0 + (bc0 & 15) * 8;
    const __half* bsrc1 = g_wh + (size_t)(bc1 >> 4) * 512 + n0 + (bc1 & 15) * 8;

    // ldmatrix per-lane bases (warp covers 64 N-columns = 128 bytes)
    const int lm_row = ((lid >> 3) & 1) * 8 + (lid & 7);
    const int lm_col = (lid >> 4) * 16;             // bytes
    const uint32_t a_lm = sA + (uint32_t)((warp_m * 32 + lm_row) * A_STRIDE_B + lm_col);
    const uint32_t b_lm = sB + (uint32_t)(lm_row * B_STRIDE_B + warp_n * 128 + lm_col);

    float c[2][8][4];
    #pragma unroll
    for (int mt = 0; mt < 2; mt++)
        #pragma unroll
        for (int nt = 0; nt < 8; nt++)
            #pragma unroll
            for (int e = 0; e < 4; e++) c[mt][nt][e] = 0.f;

    // ---- prologue: issue stages 0, 1 ----
    #pragma unroll
    for (int s = 0; s < N_STAGE - 1; s++) {
        const uint32_t ab = sA + s * A_STAGE_B;
        const uint32_t bb = sB + s * B_STAGE_B;
        asm volatile("cp.async.cg.shared.global [%0], [%1], 16;" :: "r"(ab + adst0), "l"(asrc0 + s * 32));
        asm volatile("cp.async.cg.shared.global [%0], [%1], 16;" :: "r"(ab + adst1), "l"(asrc1 + s * 32));
        asm volatile("cp.async.cg.shared.global [%0], [%1], 16;" :: "r"(bb + bdst0), "l"(bsrc0 + (size_t)s * 32 * 512));
        asm volatile("cp.async.cg.shared.global [%0], [%1], 16;" :: "r"(bb + bdst1), "l"(bsrc1 + (size_t)s * 32 * 512));
        asm volatile("cp.async.commit_group;");
    }

    int cstage = 0, pstage = N_STAGE - 1;
    #pragma unroll 1
    for (int kc = 0; kc < 16; kc++) {
        asm volatile("cp.async.wait_group %0;" :: "n"(N_STAGE - 2));
        __syncthreads();

        // issue stage kc+2 into buf pstage (held stage kc-1: all warps done with it)
        if (kc + N_STAGE - 1 < 16) {
            const int s = kc + N_STAGE - 1;
            const uint32_t ab = sA + pstage * A_STAGE_B;
            const uint32_t bb = sB + pstage * B_STAGE_B;
            asm volatile("cp.async.cg.shared.global [%0], [%1], 16;" :: "r"(ab + adst0), "l"(asrc0 + s * 32));
            asm volatile("cp.async.cg.shared.global [%0], [%1], 16;" :: "r"(ab + adst1), "l"(asrc1 + s * 32));
            asm volatile("cp.async.cg.shared.global [%0], [%1], 16;" :: "r"(bb + bdst0), "l"(bsrc0 + (size_t)s * 32 * 512));
            asm volatile("cp.async.cg.shared.global [%0], [%1], 16;" :: "r"(bb + bdst1), "l"(bsrc1 + (size_t)s * 32 * 512));
        }
        asm volatile("cp.async.commit_group;");

        const uint32_t abuf = a_lm + cstage * A_STAGE_B;
        const uint32_t bbuf = b_lm + cstage * B_STAGE_B;
        #pragma unroll
        for (int ks = 0; ks < 2; ks++) {
            uint32_t a[2][4], bf[8][2];
            #pragma unroll
            for (int mt = 0; mt < 2; mt++) {
                asm volatile("ldmatrix.sync.aligned.m8n8.x4.shared.b16 {%0,%1,%2,%3}, [%4];"
                             : "=r"(a[mt][0]), "=r"(a[mt][1]), "=r"(a[mt][2]), "=r"(a[mt][3])
                             : "r"(abuf + (uint32_t)(mt * 16 * A_STRIDE_B + ks * 32)));
            }
            #pragma unroll
            for (int i = 0; i < 4; i++) {
                asm volatile("ldmatrix.sync.aligned.m8n8.x4.trans.shared.b16 {%0,%1,%2,%3}, [%4];"
                             : "=r"(bf[2*i][0]), "=r"(bf[2*i][1]),
                               "=r"(bf[2*i+1][0]), "=r"(bf[2*i+1][1])
                             : "r"(bbuf + (uint32_t)(ks * 16 * B_STRIDE_B + i * 32)));
            }
            #pragma unroll
            for (int mt = 0; mt < 2; mt++)
                #pragma unroll
                for (int nt = 0; nt < 8; nt++) {
                    asm volatile(
                        "mma.sync.aligned.m16n8k16.row.col.f32.f16.f16.f32 "
                        "{%0,%1,%2,%3}, {%4,%5,%6,%7}, {%8,%9}, {%0,%1,%2,%3};"
                        : "+f"(c[mt][nt][0]), "+f"(c[mt][nt][1]),
                          "+f"(c[mt][nt][2]), "+f"(c[mt][nt][3])
                        : "r"(a[mt][0]), "r"(a[mt][1]), "r"(a[mt][2]), "r"(a[mt][3]),
                          "r"(bf[nt][0]), "r"(bf[nt][1]));
                }
        }
        cstage = (cstage + 1 == N_STAGE) ? 0 : cstage + 1;
        pstage = (pstage + 1 == N_STAGE) ? 0 : pstage + 1;
    }

    // ---- epilogue: out = c + x ----
    // FIX: warp covers 64 N-columns, so column base is warp_n*64 (was warp_n*128,
    // which wrote past the tile/tensor -> illegal memory access).
    const int rbase = m0 + warp_m * 32 + (lid >> 2);
    const int cbase = n0 + warp_n * 64 + (lid & 3) * 2;
    #pragma unroll
    for (int mt = 0; mt < 2; mt++) {
        #pragma unroll
        for (int nt = 0; nt < 8; nt++) {
            int col = cbase + nt * 8;
            {
                size_t o = (size_t)(rbase + mt * 16) * 512 + col;
                float2 xv = *reinterpret_cast<const float2*>(x + o);
                float2 r = make_float2(c[mt][nt][0] + xv.x, c[mt][nt][1] + xv.y);
                *reinterpret_cast<float2*>(out + o) = r;
            }
            {
                size_t o = (size_t)(rbase + mt * 16 + 8) * 512 + col;
                float2 xv = *reinterpret_cast<const float2*>(x + o);
                float2 r = make_float2(c[mt][nt][2] + xv.x, c[mt][nt][3] + xv.y);
                *reinterpret_cast<float2*>(out + o) = r;
            }
        }
    }
}

// ---------------- launch ----------------
extern "C" void kernel_launch(void* const* d_in, const int* in_sizes, int n_in,
                              void* d_out, int out_size) {
    const float* x        = (const float*)d_in[0];
    const float* adj_mask = (const float*)d_in[1];
    const float* W        = (const float*)d_in[2];
    const float* a_l      = (const float*)d_in[3];
    const float* a_r      = (const float*)d_in[4];
    float* out = (float*)d_out;

    cudaFuncSetAttribute(gemm_kernel, cudaFuncAttributeMaxDynamicSharedMemorySize, GEMM_SMEM);

    prep_w_kernel<<<512, 512>>>(W);
    prep_wa_kernel<<<64, 256>>>(W, a_l, a_r);
    attn_kernel<<<B_SZ, 128>>>(x, adj_mask);
    gemm_kernel<<<dim3(4, 1536), 256, GEMM_SMEM>>>(x, out);
}